// round 2
// baseline (speedup 1.0000x reference)
#include <cuda_runtime.h>
#include <cuda_bf16.h>
#include <cstdint>

// ---------------- problem dims ----------------
#define BB 64
#define TT 2048
#define EE 256
#define AA 128
#define PP 128
#define RR 1024
#define DD 1024
#define HH 256
#define FF 32
#define KK 31
#define PAD 15
#define NEG_INF (-1e30f)

// ---------------- scratch (device globals, no allocs) ----------------
__device__ float g_gates[BB * 4096];
__device__ float g_ah[BB * RR];
__device__ float g_ac[BB * RR];
__device__ float g_dh[BB * DD];
__device__ float g_dc[BB * DD];
__device__ float g_pq[BB * AA];
__device__ float g_energy[BB * TT];
__device__ float g_ctx_part[BB * 8 * EE];
__device__ float g_ctx[BB * EE];
__device__ int   g_maskmode;

__device__ __forceinline__ float tanhfast(float x) {
    float y;
    asm("tanh.approx.f32 %0, %1;" : "=f"(y) : "f"(x));
    return y;
}
__device__ __forceinline__ float sigmoidf(float x) {
    return 1.0f / (1.0f + __expf(-x));
}

// ---------------- mask dtype detector ----------------
// mode 0: int32 {0,1}; mode 1: float32 {0.0,1.0}; mode 2: uint8 bytes
__global__ void detect_mask_k(const unsigned int* mw) {
    int tid = threadIdx.x;
    int n01 = 0, nf = 0;
    for (int i = tid; i < 4096; i += 256) {
        unsigned v = mw[i];
        n01 |= (v > 1u);
        nf  |= (v != 0u && v != 0x3F800000u);
    }
    int a  = __syncthreads_or(n01);
    int bf = __syncthreads_or(nf);
    if (tid == 0) g_maskmode = a ? (bf ? 2 : 1) : 0;
}

// ---------------- generic M=64 GEMM: out[64,N] = sum_seg A_seg @ W_seg^T + biases ----
struct Seg { const float* A; const float* W; int lda; int ldw; int K; };
struct Segs3 { Seg s[3]; int n; };

__global__ void gemm64(Segs3 segs, const float* bias1, const float* bias2,
                       float* out, int ldo) {
    __shared__ float As[16][64];
    __shared__ float Ws[16][64];
    int tid = threadIdx.x;
    int j0  = blockIdx.x * 64;
    int tx  = tid & 15, ty = tid >> 4;      // compute roles
    int ml  = tid & 63, kk4 = tid >> 6;     // loader roles
    float acc[4][4];
#pragma unroll
    for (int i = 0; i < 4; i++)
#pragma unroll
        for (int j = 0; j < 4; j++) acc[i][j] = 0.f;

    for (int sg = 0; sg < segs.n; sg++) {
        const float* Aseg = segs.s[sg].A;
        const float* Wseg = segs.s[sg].W;
        int lda = segs.s[sg].lda, ldw = segs.s[sg].ldw, K = segs.s[sg].K;
        for (int k0 = 0; k0 < K; k0 += 16) {
            float4 av = *(const float4*)(Aseg + (size_t)ml * lda + k0 + kk4 * 4);
            float4 wv = *(const float4*)(Wseg + (size_t)(j0 + ml) * ldw + k0 + kk4 * 4);
            As[kk4 * 4 + 0][ml] = av.x;
            As[kk4 * 4 + 1][ml] = av.y;
            As[kk4 * 4 + 2][ml] = av.z;
            As[kk4 * 4 + 3][ml] = av.w;
            Ws[kk4 * 4 + 0][ml] = wv.x;
            Ws[kk4 * 4 + 1][ml] = wv.y;
            Ws[kk4 * 4 + 2][ml] = wv.z;
            Ws[kk4 * 4 + 3][ml] = wv.w;
            __syncthreads();
#pragma unroll
            for (int kk = 0; kk < 16; kk++) {
                float4 a = *(const float4*)&As[kk][ty * 4];
                float4 w = *(const float4*)&Ws[kk][tx * 4];
                acc[0][0] += a.x * w.x; acc[0][1] += a.x * w.y; acc[0][2] += a.x * w.z; acc[0][3] += a.x * w.w;
                acc[1][0] += a.y * w.x; acc[1][1] += a.y * w.y; acc[1][2] += a.y * w.z; acc[1][3] += a.y * w.w;
                acc[2][0] += a.z * w.x; acc[2][1] += a.z * w.y; acc[2][2] += a.z * w.z; acc[2][3] += a.z * w.w;
                acc[3][0] += a.w * w.x; acc[3][1] += a.w * w.y; acc[3][2] += a.w * w.z; acc[3][3] += a.w * w.w;
            }
            __syncthreads();
        }
    }
#pragma unroll
    for (int i = 0; i < 4; i++) {
        int m = ty * 4 + i;
#pragma unroll
        for (int j = 0; j < 4; j++) {
            int n = j0 + tx * 4 + j;
            float bb = 0.f;
            if (bias1) bb += bias1[n];
            if (bias2) bb += bias2[n];
            out[(size_t)m * ldo + n] = acc[i][j] + bb;
        }
    }
}

// ---------------- LSTM pointwise (gate order i,f,g,o) ----------------
__global__ void lstm_point_k(const float* gates, const float* c_in,
                             float* h_out, float* c_out) {
    int idx = blockIdx.x * 256 + threadIdx.x;  // 64*1024
    int b = idx >> 10, r = idx & 1023;
    const float* g = gates + (size_t)b * 4096;
    float gi = g[r], gf = g[1024 + r], gg = g[2048 + r], go = g[3072 + r];
    float c  = c_in[idx];
    float c2 = sigmoidf(gf) * c + sigmoidf(gi) * tanhf(gg);
    float h2 = sigmoidf(go) * tanhf(c2);
    c_out[idx] = c2;
    h_out[idx] = h2;
}

// ---------------- fused conv(31) + location FC + tanh energy ----------------
__global__ void energies_k(const float* att_w, const float* att_w_cum,
                           const float* pm, const float* pq,
                           const float* W_loc, const float* W_lfc,
                           const float* W_v, const void* mask,
                           float* energy) {
    __shared__ float s_aw0[256 + 30];
    __shared__ float s_aw1[256 + 30];
    __shared__ float s_pq[AA];
    __shared__ float s_wv[AA];
    __shared__ float s_wl[2 * KK * FF];   // [c][k][f]
    __shared__ float s_wlfc[AA * FF];     // [a][f]

    int tid = threadIdx.x;
    int b = blockIdx.y;
    int t0 = blockIdx.x * 256;
    int t = t0 + tid;

    for (int i = tid; i < 286; i += 256) {
        int gidx = t0 - PAD + i;
        bool inb = (gidx >= 0 && gidx < TT);
        s_aw0[i] = inb ? att_w[(size_t)b * TT + gidx] : 0.f;
        s_aw1[i] = inb ? att_w_cum[(size_t)b * TT + gidx] : 0.f;
    }
    for (int i = tid; i < 2 * KK * FF; i += 256) {
        int c = i / (KK * FF);
        int r = i % (KK * FF);
        int k = r / FF, f = r % FF;
        s_wl[i] = W_loc[f * (2 * KK) + c * KK + k];
    }
    for (int i = tid; i < AA * FF; i += 256) s_wlfc[i] = W_lfc[i];
    if (tid < AA) { s_pq[tid] = pq[b * AA + tid]; s_wv[tid] = W_v[tid]; }
    __syncthreads();

    // conv -> locf registers
    float locf[FF];
#pragma unroll
    for (int f = 0; f < FF; f++) locf[f] = 0.f;
    for (int k = 0; k < KK; k++) {
        float a0 = s_aw0[tid + k];
        float a1 = s_aw1[tid + k];
        const float* w0 = &s_wl[k * FF];
        const float* w1 = &s_wl[KK * FF + k * FF];
#pragma unroll
        for (int f = 0; f < FF; f++) locf[f] += a0 * w0[f] + a1 * w1[f];
    }

    // FC + tanh energy
    float e = 0.f;
    const float* pmrow = pm + ((size_t)b * TT + t) * AA;
    for (int a = 0; a < AA; a++) {
        const float* wl = &s_wlfc[a * FF];
        float la = 0.f;
#pragma unroll
        for (int f = 0; f < FF; f++) la += locf[f] * wl[f];
        float x = s_pq[a] + pmrow[a] + la;
        e += tanhfast(x) * s_wv[a];
    }

    // mask
    size_t mi = (size_t)b * TT + t;
    int mm = g_maskmode;
    bool masked;
    if (mm == 0)      masked = (((const int*)mask)[mi] != 0);
    else if (mm == 1) masked = (((const float*)mask)[mi] != 0.f);
    else              masked = (((const unsigned char*)mask)[mi] != 0);
    energy[mi] = masked ? NEG_INF : e;
}

// ---------------- softmax over T per batch, writes weights output ----------------
__global__ void softmax_k(const float* energy, float* wout) {
    __shared__ float red[256];
    int b = blockIdx.x, tid = threadIdx.x;
    const float* er = energy + (size_t)b * TT;
    float m = -3.0e38f;
    for (int t = tid; t < TT; t += 256) m = fmaxf(m, er[t]);
    red[tid] = m; __syncthreads();
    for (int s = 128; s > 0; s >>= 1) {
        if (tid < s) red[tid] = fmaxf(red[tid], red[tid + s]);
        __syncthreads();
    }
    m = red[0]; __syncthreads();
    float sum = 0.f;
    for (int t = tid; t < TT; t += 256) sum += __expf(er[t] - m);
    red[tid] = sum; __syncthreads();
    for (int s = 128; s > 0; s >>= 1) {
        if (tid < s) red[tid] += red[tid + s];
        __syncthreads();
    }
    float inv = 1.0f / red[0];
    for (int t = tid; t < TT; t += 256)
        wout[(size_t)b * TT + t] = __expf(er[t] - m) * inv;
}

// ---------------- context: partial over T-chunks (deterministic) ----------------
__global__ void ctx_part_k(const float* w, const float* memory) {
    int b = blockIdx.y, tc = blockIdx.x, e = threadIdx.x;  // 256 threads
    int t0 = tc * 256;
    const float* mrow = memory + ((size_t)b * TT + t0) * EE + e;
    const float* wrow = w + (size_t)b * TT + t0;
    float acc = 0.f;
    for (int i = 0; i < 256; i++) acc += wrow[i] * mrow[(size_t)i * EE];
    g_ctx_part[((size_t)b * 8 + tc) * EE + e] = acc;
}

__global__ void ctx_red_k() {
    int b = blockIdx.x, e = threadIdx.x;
    float s = 0.f;
#pragma unroll
    for (int p = 0; p < 8; p++) s += g_ctx_part[((size_t)b * 8 + p) * EE + e];
    g_ctx[b * EE + e] = s;
}

// ---------------- stop gate head ----------------
__global__ void stop_k(const float* W_gate, const float* b_gate, float* out) {
    __shared__ float red[128];
    int b = blockIdx.x, tid = threadIdx.x;
    float s = 0.f;
    for (int i = tid; i < DD; i += 128) s += g_dh[b * DD + i] * W_gate[i];
    for (int i = tid; i < EE; i += 128) s += g_ctx[b * EE + i] * W_gate[DD + i];
    red[tid] = s; __syncthreads();
    for (int st = 64; st > 0; st >>= 1) {
        if (tid < st) red[tid] += red[tid + st];
        __syncthreads();
    }
    if (tid == 0) out[b] = red[0] + b_gate[0];
}

// ---------------- launch ----------------
extern "C" void kernel_launch(void* const* d_in, const int* in_sizes, int n_in,
                              void* d_out, int out_size) {
    const float* last_frame = (const float*)d_in[0];
    const float* att_h      = (const float*)d_in[1];
    const float* att_c      = (const float*)d_in[2];
    const float* att_w      = (const float*)d_in[3];
    const float* att_w_cum  = (const float*)d_in[4];
    const float* att_ctx    = (const float*)d_in[5];
    const float* dec_h      = (const float*)d_in[6];
    const float* dec_c      = (const float*)d_in[7];
    const float* memory     = (const float*)d_in[8];
    const float* pm         = (const float*)d_in[9];
    const float* W_ih_a     = (const float*)d_in[10];
    const float* W_hh_a     = (const float*)d_in[11];
    const float* b_ih_a     = (const float*)d_in[12];
    const float* b_hh_a     = (const float*)d_in[13];
    const float* W_q        = (const float*)d_in[14];
    const float* W_v        = (const float*)d_in[15];
    const float* W_loc      = (const float*)d_in[16];
    const float* W_lfc      = (const float*)d_in[17];
    const float* W_ih_d     = (const float*)d_in[18];
    const float* W_hh_d     = (const float*)d_in[19];
    const float* b_ih_d     = (const float*)d_in[20];
    const float* b_hh_d     = (const float*)d_in[21];
    const float* W_proj     = (const float*)d_in[22];
    const float* b_proj     = (const float*)d_in[23];
    const float* W_gate     = (const float*)d_in[24];
    const float* b_gate     = (const float*)d_in[25];
    const void*  mask       = d_in[26];

    float* out      = (float*)d_out;                // decoder_output [64,256]
    float* stop_out = out + BB * HH;                // [64]
    float* w_out    = out + BB * HH + BB;           // weights [64,2048]

    float *p_gates, *p_ah, *p_ac, *p_dh, *p_dc, *p_pq, *p_energy;
    cudaGetSymbolAddress((void**)&p_gates, g_gates);
    cudaGetSymbolAddress((void**)&p_ah, g_ah);
    cudaGetSymbolAddress((void**)&p_ac, g_ac);
    cudaGetSymbolAddress((void**)&p_dh, g_dh);
    cudaGetSymbolAddress((void**)&p_dc, g_dc);
    cudaGetSymbolAddress((void**)&p_pq, g_pq);
    cudaGetSymbolAddress((void**)&p_energy, g_energy);

    detect_mask_k<<<1, 256>>>((const unsigned int*)mask);

    // attention LSTM gates: concat(last_frame, att_ctx) @ W_ih_a^T + att_h @ W_hh_a^T + b
    {
        Segs3 s{}; s.n = 3;
        s.s[0] = { last_frame, W_ih_a,        PP, PP + EE, PP };
        s.s[1] = { att_ctx,    W_ih_a + PP,   EE, PP + EE, EE };
        s.s[2] = { att_h,      W_hh_a,        RR, RR,      RR };
        gemm64<<<4 * RR / 64, 256>>>(s, b_ih_a, b_hh_a, p_gates, 4 * RR);
    }
    lstm_point_k<<<BB * RR / 256, 256>>>(p_gates, att_c, p_ah, p_ac);

    // processed query
    {
        Segs3 s{}; s.n = 1;
        s.s[0] = { p_ah, W_q, RR, RR, RR };
        gemm64<<<AA / 64, 256>>>(s, nullptr, nullptr, p_pq, AA);
    }

    energies_k<<<dim3(TT / 256, BB), 256>>>(att_w, att_w_cum, pm, p_pq,
                                            W_loc, W_lfc, W_v, mask, p_energy);
    softmax_k<<<BB, 256>>>(p_energy, w_out);
    ctx_part_k<<<dim3(8, BB), 256>>>(w_out, memory);
    ctx_red_k<<<BB, EE>>>();

    // decoder LSTM gates: concat(ah, ctx) @ W_ih_d^T + dec_h @ W_hh_d^T + b
    {
        float* p_ctx; cudaGetSymbolAddress((void**)&p_ctx, g_ctx);
        Segs3 s{}; s.n = 3;
        s.s[0] = { p_ah,  W_ih_d,        RR, RR + EE, RR };
        s.s[1] = { p_ctx, W_ih_d + RR,   EE, RR + EE, EE };
        s.s[2] = { dec_h, W_hh_d,        DD, DD,      DD };
        gemm64<<<4 * DD / 64, 256>>>(s, b_ih_d, b_hh_d, p_gates, 4 * DD);
    }
    lstm_point_k<<<BB * DD / 256, 256>>>(p_gates, dec_c, p_dh, p_dc);

    // projection head -> decoder_output
    {
        float* p_ctx; cudaGetSymbolAddress((void**)&p_ctx, g_ctx);
        Segs3 s{}; s.n = 2;
        s.s[0] = { p_dh,  W_proj,      DD, DD + EE, DD };
        s.s[1] = { p_ctx, W_proj + DD, EE, DD + EE, EE };
        gemm64<<<HH / 64, 256>>>(s, b_proj, nullptr, out, HH);
    }
    stop_k<<<BB, 128>>>(W_gate, b_gate, stop_out);
}

// round 5
// speedup vs baseline: 2.1235x; 2.1235x over previous
#include <cuda_runtime.h>
#include <cuda_bf16.h>
#include <cstdint>

#define BB 64
#define TT 2048
#define EE 256
#define AA 128
#define PP 128
#define RR 1024
#define DD 1024
#define HH 256
#define FF 32
#define KK 31
#define PAD 15
#define NEG_INF (-1e30f)

typedef unsigned long long ull;

// ---------------- scratch ----------------
__device__ float g_part[4 * BB * 4096];   // split-K partials (max 4MB)
__device__ float g_gatesN[1];             // unused sentinel
__device__ float g_ah[BB * RR];
__device__ float g_ac[BB * RR];
__device__ float g_dh[BB * DD];
__device__ float g_dc[BB * DD];
__device__ float g_pq[BB * AA];
__device__ float g_energy[BB * TT];
__device__ float g_ctx_part[BB * 8 * EE];
__device__ float g_ctx[BB * EE];
__device__ int   g_maskmode;

__device__ __forceinline__ float tanhfast(float x) {
    float y; asm("tanh.approx.f32 %0, %1;" : "=f"(y) : "f"(x)); return y;
}
__device__ __forceinline__ float sigmoidf(float x) {
    return 1.0f / (1.0f + __expf(-x));
}
__device__ __forceinline__ ull pack2(float lo, float hi) {
    ull r; asm("mov.b64 %0, {%1, %2};" : "=l"(r) : "f"(lo), "f"(hi)); return r;
}
__device__ __forceinline__ ull fma2(ull a, ull b, ull c) {
    ull r; asm("fma.rn.f32x2 %0, %1, %2, %3;" : "=l"(r) : "l"(a), "l"(b), "l"(c)); return r;
}
__device__ __forceinline__ float2 unpack2(ull v) {
    float2 f; asm("mov.b64 {%0, %1}, %2;" : "=f"(f.x), "=f"(f.y) : "l"(v)); return f;
}

// ---------------- mask dtype detector ----------------
__global__ void detect_mask_k(const unsigned int* mw) {
    int tid = threadIdx.x;
    int n01 = 0, nf = 0;
    for (int i = tid; i < 4096; i += 256) {
        unsigned v = mw[i];
        n01 |= (v > 1u);
        nf  |= (v != 0u && v != 0x3F800000u);
    }
    int a  = __syncthreads_or(n01);
    int bf = __syncthreads_or(nf);
    if (tid == 0) g_maskmode = a ? (bf ? 2 : 1) : 0;
}

// ---------------- split-K GEMM: part[sp][64, N-tile] = sum of assigned k-chunks ----
struct Seg { const float* A; const float* W; int lda; int ldw; int K; };
struct Segs3 { Seg s[3]; int n; };

__global__ __launch_bounds__(256) void gemm64s(Segs3 segs, float* part, int ldo, int splitK) {
    __shared__ float As[16][64];
    __shared__ float Ws[16][64];
    int tid = threadIdx.x;
    int j0  = blockIdx.x * 64;
    int sp  = blockIdx.y;
    int tx  = tid & 15, ty = tid >> 4;
    int ml  = tid & 63, kk4 = tid >> 6;
    ull acc[4][2];
#pragma unroll
    for (int i = 0; i < 4; i++) { acc[i][0] = 0ull; acc[i][1] = 0ull; }

    int cidx = 0;
    for (int sg = 0; sg < segs.n; sg++) {
        const float* Aseg = segs.s[sg].A;
        const float* Wseg = segs.s[sg].W;
        int lda = segs.s[sg].lda, ldw = segs.s[sg].ldw, K = segs.s[sg].K;
        for (int k0 = 0; k0 < K; k0 += 16) {
            if ((cidx++ % splitK) != sp) continue;
            float4 av = *(const float4*)(Aseg + (size_t)ml * lda + k0 + kk4 * 4);
            float4 wv = *(const float4*)(Wseg + (size_t)(j0 + ml) * ldw + k0 + kk4 * 4);
            As[kk4 * 4 + 0][ml] = av.x;
            As[kk4 * 4 + 1][ml] = av.y;
            As[kk4 * 4 + 2][ml] = av.z;
            As[kk4 * 4 + 3][ml] = av.w;
            Ws[kk4 * 4 + 0][ml] = wv.x;
            Ws[kk4 * 4 + 1][ml] = wv.y;
            Ws[kk4 * 4 + 2][ml] = wv.z;
            Ws[kk4 * 4 + 3][ml] = wv.w;
            __syncthreads();
#pragma unroll
            for (int kk = 0; kk < 16; kk++) {
                float4 a = *(const float4*)&As[kk][ty * 4];
                ulonglong2 w = *(const ulonglong2*)&Ws[kk][tx * 4];
                ull a0 = pack2(a.x, a.x), a1 = pack2(a.y, a.y);
                ull a2 = pack2(a.z, a.z), a3 = pack2(a.w, a.w);
                acc[0][0] = fma2(a0, w.x, acc[0][0]); acc[0][1] = fma2(a0, w.y, acc[0][1]);
                acc[1][0] = fma2(a1, w.x, acc[1][0]); acc[1][1] = fma2(a1, w.y, acc[1][1]);
                acc[2][0] = fma2(a2, w.x, acc[2][0]); acc[2][1] = fma2(a2, w.y, acc[2][1]);
                acc[3][0] = fma2(a3, w.x, acc[3][0]); acc[3][1] = fma2(a3, w.y, acc[3][1]);
            }
            __syncthreads();
        }
    }
    float* dst = part + (size_t)sp * 64 * ldo;
#pragma unroll
    for (int i = 0; i < 4; i++) {
        int m = ty * 4 + i;
        float2 r0 = unpack2(acc[i][0]);
        float2 r1 = unpack2(acc[i][1]);
        float4 v = make_float4(r0.x, r0.y, r1.x, r1.y);
        *(float4*)(dst + (size_t)m * ldo + j0 + tx * 4) = v;
    }
}

// ---------------- partial reduce (+optional bias) ----------------
__global__ void reduce_part_k(const float* part, int nsplit, int total, int ldo,
                              const float* bias, float* out) {
    int idx = blockIdx.x * 256 + threadIdx.x;
    if (idx >= total) return;
    float s = 0.f;
    for (int p = 0; p < nsplit; p++) s += part[(size_t)p * total + idx];
    if (bias) s += bias[idx % ldo];
    out[idx] = s;
}

// ---------------- LSTM pointwise fused with split reduce ----------------
__global__ void lstm_point_k(const float* part, int nsplit,
                             const float* b1, const float* b2,
                             const float* c_in, float* h_out, float* c_out) {
    int idx = blockIdx.x * 256 + threadIdx.x;  // 64*1024
    int b = idx >> 10, r = idx & 1023;
    size_t base = (size_t)b * 4096;
    float g[4];
#pragma unroll
    for (int gt = 0; gt < 4; gt++) g[gt] = b1[gt * 1024 + r] + b2[gt * 1024 + r];
    for (int p = 0; p < nsplit; p++) {
        const float* pp = part + (size_t)p * BB * 4096 + base + r;
#pragma unroll
        for (int gt = 0; gt < 4; gt++) g[gt] += pp[gt * 1024];
    }
    float c  = c_in[idx];
    float c2 = sigmoidf(g[1]) * c + sigmoidf(g[0]) * tanhf(g[2]);
    float h2 = sigmoidf(g[3]) * tanhf(c2);
    c_out[idx] = c2;
    h_out[idx] = h2;
}

// ---------------- fused conv(31) + location FC + tanh energy (f32x2) ----------------
__global__ __launch_bounds__(256) void energies_k(
        const float* att_w, const float* att_w_cum,
        const float* pm, const float* pq,
        const float* W_loc, const float* W_lfc,
        const float* W_v, const void* mask, float* energy) {
    __shared__ float s_aw0[256 + 30];
    __shared__ float s_aw1[256 + 30];
    __shared__ float s_pq[AA];
    __shared__ float s_wv[AA];
    __shared__ ulonglong2 s_wl2[2][KK][8];     // [c][k][f-pair pairs]
    __shared__ ulonglong2 s_wlfc2[AA][8];      // [a][f-pairs]

    int tid = threadIdx.x;
    int b = blockIdx.y;
    int t0 = blockIdx.x * 256;
    int t = t0 + tid;

    for (int i = tid; i < 286; i += 256) {
        int gidx = t0 - PAD + i;
        bool inb = (gidx >= 0 && gidx < TT);
        s_aw0[i] = inb ? att_w[(size_t)b * TT + gidx] : 0.f;
        s_aw1[i] = inb ? att_w_cum[(size_t)b * TT + gidx] : 0.f;
    }
    // W_loc layout [F][2][K]; pack pairs over F
    for (int i = tid; i < 2 * KK * 16; i += 256) {
        int c = i / (KK * 16);
        int r = i % (KK * 16);
        int k = r / 16, fp = r % 16;
        float lo = W_loc[(2 * fp + 0) * (2 * KK) + c * KK + k];
        float hi = W_loc[(2 * fp + 1) * (2 * KK) + c * KK + k];
        ((ull*)s_wl2)[c * KK * 16 + k * 16 + fp] = pack2(lo, hi);
    }
    // W_lfc layout [A][F], F contiguous -> direct vector copy
    for (int i = tid; i < AA * 8; i += 256)
        ((ulonglong2*)s_wlfc2)[i] = ((const ulonglong2*)W_lfc)[i];
    if (tid < AA) { s_pq[tid] = pq[b * AA + tid]; s_wv[tid] = W_v[tid]; }
    __syncthreads();

    // conv -> locf2 registers (16 f32x2 = 32 filters)
    ull locf2[16];
#pragma unroll
    for (int i = 0; i < 16; i++) locf2[i] = 0ull;
    for (int k = 0; k < KK; k++) {
        ull a0 = pack2(s_aw0[tid + k], s_aw0[tid + k]);
        ull a1 = pack2(s_aw1[tid + k], s_aw1[tid + k]);
#pragma unroll
        for (int i = 0; i < 8; i++) {
            ulonglong2 w0 = s_wl2[0][k][i];
            ulonglong2 w1 = s_wl2[1][k][i];
            locf2[2 * i]     = fma2(a0, w0.x, locf2[2 * i]);
            locf2[2 * i + 1] = fma2(a0, w0.y, locf2[2 * i + 1]);
            locf2[2 * i]     = fma2(a1, w1.x, locf2[2 * i]);
            locf2[2 * i + 1] = fma2(a1, w1.y, locf2[2 * i + 1]);
        }
    }

    // FC + tanh energy; 2 attention dims per iteration, 4 indep chains
    const float2* pmrow2 = (const float2*)(pm + ((size_t)b * TT + t) * AA);
    float e = 0.f;
    for (int a = 0; a < AA; a += 2) {
        ull ac0 = 0ull, ac1 = 0ull, ac2 = 0ull, ac3 = 0ull;
#pragma unroll
        for (int i = 0; i < 8; i++) {
            ulonglong2 w0 = s_wlfc2[a][i];
            ulonglong2 w1 = s_wlfc2[a + 1][i];
            ac0 = fma2(locf2[2 * i],     w0.x, ac0);
            ac1 = fma2(locf2[2 * i + 1], w0.y, ac1);
            ac2 = fma2(locf2[2 * i],     w1.x, ac2);
            ac3 = fma2(locf2[2 * i + 1], w1.y, ac3);
        }
        float2 f0 = unpack2(ac0), f1 = unpack2(ac1);
        float2 f2 = unpack2(ac2), f3 = unpack2(ac3);
        float la0 = (f0.x + f0.y) + (f1.x + f1.y);
        float la1 = (f2.x + f2.y) + (f3.x + f3.y);
        float2 p = pmrow2[a >> 1];
        float x0 = s_pq[a] + p.x + la0;
        float x1 = s_pq[a + 1] + p.y + la1;
        e += tanhfast(x0) * s_wv[a];
        e += tanhfast(x1) * s_wv[a + 1];
    }

    size_t mi = (size_t)b * TT + t;
    int mm = g_maskmode;
    bool masked;
    if (mm == 0)      masked = (((const int*)mask)[mi] != 0);
    else if (mm == 1) masked = (((const float*)mask)[mi] != 0.f);
    else              masked = (((const unsigned char*)mask)[mi] != 0);
    energy[mi] = masked ? NEG_INF : e;
}

// ---------------- softmax (exp cached in smem) ----------------
__global__ void softmax_k(const float* energy, float* wout) {
    __shared__ float red[256];
    __shared__ float s_e[TT];
    int b = blockIdx.x, tid = threadIdx.x;
    const float* er = energy + (size_t)b * TT;
    float m = -3.0e38f;
    for (int t = tid; t < TT; t += 256) {
        float v = er[t];
        s_e[t] = v;
        m = fmaxf(m, v);
    }
    red[tid] = m; __syncthreads();
    for (int s = 128; s > 0; s >>= 1) {
        if (tid < s) red[tid] = fmaxf(red[tid], red[tid + s]);
        __syncthreads();
    }
    m = red[0]; __syncthreads();
    float sum = 0.f;
    for (int t = tid; t < TT; t += 256) {
        float ex = __expf(s_e[t] - m);
        s_e[t] = ex;
        sum += ex;
    }
    red[tid] = sum; __syncthreads();
    for (int s = 128; s > 0; s >>= 1) {
        if (tid < s) red[tid] += red[tid + s];
        __syncthreads();
    }
    float inv = 1.0f / red[0];
    for (int t = tid; t < TT; t += 256)
        wout[(size_t)b * TT + t] = s_e[t] * inv;
}

// ---------------- context partials ----------------
__global__ void ctx_part_k(const float* w, const float* memory) {
    __shared__ float s_w[256];
    int b = blockIdx.y, tc = blockIdx.x, e = threadIdx.x;
    int t0 = tc * 256;
    s_w[e] = w[(size_t)b * TT + t0 + e];
    __syncthreads();
    const float* mrow = memory + ((size_t)b * TT + t0) * EE + e;
    float a0 = 0.f, a1 = 0.f, a2 = 0.f, a3 = 0.f;
    for (int i = 0; i < 256; i += 4) {
        a0 += s_w[i + 0] * mrow[(size_t)(i + 0) * EE];
        a1 += s_w[i + 1] * mrow[(size_t)(i + 1) * EE];
        a2 += s_w[i + 2] * mrow[(size_t)(i + 2) * EE];
        a3 += s_w[i + 3] * mrow[(size_t)(i + 3) * EE];
    }
    g_ctx_part[((size_t)b * 8 + tc) * EE + e] = (a0 + a1) + (a2 + a3);
}

__global__ void ctx_red_k() {
    int b = blockIdx.x, e = threadIdx.x;
    float s = 0.f;
#pragma unroll
    for (int p = 0; p < 8; p++) s += g_ctx_part[((size_t)b * 8 + p) * EE + e];
    g_ctx[b * EE + e] = s;
}

// ---------------- stop gate head ----------------
__global__ void stop_k(const float* W_gate, const float* b_gate, float* out) {
    __shared__ float red[128];
    int b = blockIdx.x, tid = threadIdx.x;
    float s = 0.f;
    for (int i = tid; i < DD; i += 128) s += g_dh[b * DD + i] * W_gate[i];
    for (int i = tid; i < EE; i += 128) s += g_ctx[b * EE + i] * W_gate[DD + i];
    red[tid] = s; __syncthreads();
    for (int st = 64; st > 0; st >>= 1) {
        if (tid < st) red[tid] += red[tid + st];
        __syncthreads();
    }
    if (tid == 0) out[b] = red[0] + b_gate[0];
}

// ---------------- launch ----------------
extern "C" void kernel_launch(void* const* d_in, const int* in_sizes, int n_in,
                              void* d_out, int out_size) {
    const float* last_frame = (const float*)d_in[0];
    const float* att_h      = (const float*)d_in[1];
    const float* att_c      = (const float*)d_in[2];
    const float* att_w      = (const float*)d_in[3];
    const float* att_w_cum  = (const float*)d_in[4];
    const float* att_ctx    = (const float*)d_in[5];
    const float* dec_h      = (const float*)d_in[6];
    const float* dec_c      = (const float*)d_in[7];
    const float* memory     = (const float*)d_in[8];
    const float* pm         = (const float*)d_in[9];
    const float* W_ih_a     = (const float*)d_in[10];
    const float* W_hh_a     = (const float*)d_in[11];
    const float* b_ih_a     = (const float*)d_in[12];
    const float* b_hh_a     = (const float*)d_in[13];
    const float* W_q        = (const float*)d_in[14];
    const float* W_v        = (const float*)d_in[15];
    const float* W_loc      = (const float*)d_in[16];
    const float* W_lfc      = (const float*)d_in[17];
    const float* W_ih_d     = (const float*)d_in[18];
    const float* W_hh_d     = (const float*)d_in[19];
    const float* b_ih_d     = (const float*)d_in[20];
    const float* b_hh_d     = (const float*)d_in[21];
    const float* W_proj     = (const float*)d_in[22];
    const float* b_proj     = (const float*)d_in[23];
    const float* W_gate     = (const float*)d_in[24];
    const float* b_gate     = (const float*)d_in[25];
    const void*  mask       = d_in[26];

    float* out      = (float*)d_out;                // decoder_output [64,256]
    float* stop_out = out + BB * HH;                // [64]
    float* w_out    = out + BB * HH + BB;           // weights [64,2048]

    float *p_part, *p_ah, *p_ac, *p_dh, *p_dc, *p_pq, *p_energy, *p_ctx;
    cudaGetSymbolAddress((void**)&p_part, g_part);
    cudaGetSymbolAddress((void**)&p_ah, g_ah);
    cudaGetSymbolAddress((void**)&p_ac, g_ac);
    cudaGetSymbolAddress((void**)&p_dh, g_dh);
    cudaGetSymbolAddress((void**)&p_dc, g_dc);
    cudaGetSymbolAddress((void**)&p_pq, g_pq);
    cudaGetSymbolAddress((void**)&p_energy, g_energy);
    cudaGetSymbolAddress((void**)&p_ctx, g_ctx);

    detect_mask_k<<<1, 256>>>((const unsigned int*)mask);

    // attention LSTM gates (split-K=4 -> 256 blocks)
    {
        Segs3 s{}; s.n = 3;
        s.s[0] = { last_frame, W_ih_a,      PP, PP + EE, PP };
        s.s[1] = { att_ctx,    W_ih_a + PP, EE, PP + EE, EE };
        s.s[2] = { att_h,      W_hh_a,      RR, RR,      RR };
        gemm64s<<<dim3(4 * RR / 64, 4), 256>>>(s, p_part, 4 * RR, 4);
    }
    lstm_point_k<<<BB * RR / 256, 256>>>(p_part, 4, b_ih_a, b_hh_a, att_c, p_ah, p_ac);

    // processed query (split-K=8 -> 16 blocks)
    {
        Segs3 s{}; s.n = 1;
        s.s[0] = { p_ah, W_q, RR, RR, RR };
        gemm64s<<<dim3(AA / 64, 8), 256>>>(s, p_part, AA, 8);
    }
    reduce_part_k<<<(BB * AA + 255) / 256, 256>>>(p_part, 8, BB * AA, AA, nullptr, p_pq);

    energies_k<<<dim3(TT / 256, BB), 256>>>(att_w, att_w_cum, pm, p_pq,
                                            W_loc, W_lfc, W_v, mask, p_energy);
    softmax_k<<<BB, 256>>>(p_energy, w_out);
    ctx_part_k<<<dim3(8, BB), 256>>>(w_out, memory);
    ctx_red_k<<<BB, EE>>>();

    // decoder LSTM gates (split-K=4 -> 256 blocks)
    {
        Segs3 s{}; s.n = 3;
        s.s[0] = { p_ah,  W_ih_d,      RR, RR + EE, RR };
        s.s[1] = { p_ctx, W_ih_d + RR, EE, RR + EE, EE };
        s.s[2] = { dec_h, W_hh_d,      DD, DD,      DD };
        gemm64s<<<dim3(4 * DD / 64, 4), 256>>>(s, p_part, 4 * DD, 4);
    }
    lstm_point_k<<<BB * DD / 256, 256>>>(p_part, 4, b_ih_d, b_hh_d, dec_c, p_dh, p_dc);

    // projection head (split-K=8 -> 32 blocks)
    {
        Segs3 s{}; s.n = 2;
        s.s[0] = { p_dh,  W_proj,        DD, DD + EE, DD };
        s.s[1] = { p_ctx, W_proj + DD,   EE, DD + EE, EE };
        gemm64s<<<dim3(HH / 64, 8), 256>>>(s, p_part, HH, 8);
    }
    reduce_part_k<<<(BB * HH + 255) / 256, 256>>>(p_part, 8, BB * HH, HH, b_proj, out);
    stop_k<<<BB, 128>>>(W_gate, b_gate, stop_out);
}

// round 6
// speedup vs baseline: 2.3155x; 1.0904x over previous
#include <cuda_runtime.h>
#include <cuda_bf16.h>
#include <cstdint>

#define BB 64
#define TT 2048
#define EE 256
#define AA 128
#define PP 128
#define RR 1024
#define DD 1024
#define HH 256
#define FF 32
#define KK 31
#define PAD 15
#define NEG_INF (-1e30f)

typedef unsigned long long ull;

// ---------------- scratch ----------------
__device__ float g_part[8 * BB * 4096];   // split-K partials (8MB)
__device__ float g_ah[BB * RR];
__device__ float g_ac[BB * RR];
__device__ float g_dh[BB * DD];
__device__ float g_dc[BB * DD];
__device__ float g_pq[BB * AA];
__device__ float g_energy[BB * TT];
__device__ float g_bm[BB * 8];
__device__ float g_bs[BB * 8];
__device__ float g_M[BB];
__device__ float g_inv[BB];
__device__ float g_ctx_part[BB * 8 * EE];
__device__ float g_ctx[BB * EE];
__device__ int   g_maskmode;

__device__ __forceinline__ float tanhfast(float x) {
    float y; asm("tanh.approx.f32 %0, %1;" : "=f"(y) : "f"(x)); return y;
}
__device__ __forceinline__ float sigmoidf(float x) {
    return 1.0f / (1.0f + __expf(-x));
}
__device__ __forceinline__ ull pack2(float lo, float hi) {
    ull r; asm("mov.b64 %0, {%1, %2};" : "=l"(r) : "f"(lo), "f"(hi)); return r;
}
__device__ __forceinline__ ull fma2(ull a, ull b, ull c) {
    ull r; asm("fma.rn.f32x2 %0, %1, %2, %3;" : "=l"(r) : "l"(a), "l"(b), "l"(c)); return r;
}
__device__ __forceinline__ float2 unpack2(ull v) {
    float2 f; asm("mov.b64 {%0, %1}, %2;" : "=f"(f.x), "=f"(f.y) : "l"(v)); return f;
}

// ---------------- mask dtype detector ----------------
__global__ void detect_mask_k(const unsigned int* mw) {
    int tid = threadIdx.x;
    int n01 = 0, nf = 0;
    for (int i = tid; i < 4096; i += 256) {
        unsigned v = mw[i];
        n01 |= (v > 1u);
        nf  |= (v != 0u && v != 0x3F800000u);
    }
    int a  = __syncthreads_or(n01);
    int bf = __syncthreads_or(nf);
    if (tid == 0) g_maskmode = a ? (bf ? 2 : 1) : 0;
}

// ---------------- split-K GEMM, double-buffered, f32x2 ----------------
struct Seg { const float* A; const float* W; int lda; int ldw; int K; };
struct Segs3 { Seg s[3]; int n; };

__global__ __launch_bounds__(256) void gemm64s(Segs3 segs, float* part, int ldo, int splitK) {
    __shared__ ull   As2[2][16][64];   // (a,a) duplicated pairs
    __shared__ float Wsf[2][16][64];
    int tid = threadIdx.x;
    int j0  = blockIdx.x * 64;
    int sp  = blockIdx.y;
    int tx  = tid & 15, ty = tid >> 4;
    int ml  = tid & 63, kk4 = tid >> 6;

    int n0 = segs.s[0].K >> 4;
    int n1 = (segs.n > 1) ? (segs.s[1].K >> 4) : 0;
    int n2 = (segs.n > 2) ? (segs.s[2].K >> 4) : 0;
    int ntot = n0 + n1 + n2;

    ull acc[4][2];
#pragma unroll
    for (int i = 0; i < 4; i++) { acc[i][0] = 0ull; acc[i][1] = 0ull; }

    auto fetch = [&](int g, float4& a4, float4& w4) {
        int c = g, sg = 0;
        if (c >= n0) { c -= n0; sg = 1; }
        if (sg == 1 && c >= n1) { c -= n1; sg = 2; }
        const Seg& S = segs.s[sg];
        int k = c * 16 + kk4 * 4;
        a4 = *(const float4*)(S.A + (size_t)ml * S.lda + k);
        w4 = *(const float4*)(S.W + (size_t)(j0 + ml) * S.ldw + k);
    };
    auto store = [&](int buf, const float4& a4, const float4& w4) {
        int kb = kk4 * 4;
        As2[buf][kb + 0][ml] = pack2(a4.x, a4.x);
        As2[buf][kb + 1][ml] = pack2(a4.y, a4.y);
        As2[buf][kb + 2][ml] = pack2(a4.z, a4.z);
        As2[buf][kb + 3][ml] = pack2(a4.w, a4.w);
        Wsf[buf][kb + 0][ml] = w4.x;
        Wsf[buf][kb + 1][ml] = w4.y;
        Wsf[buf][kb + 2][ml] = w4.z;
        Wsf[buf][kb + 3][ml] = w4.w;
    };

    int g = sp;
    if (g < ntot) {
        float4 a4, w4;
        fetch(g, a4, w4);
        store(0, a4, w4);
    }
    __syncthreads();

    int buf = 0;
    while (g < ntot) {
        int gn = g + splitK;
        float4 a4, w4;
        bool more = (gn < ntot);
        if (more) fetch(gn, a4, w4);
#pragma unroll
        for (int kk = 0; kk < 16; kk++) {
            const ulonglong2* ar = (const ulonglong2*)&As2[buf][kk][ty * 4];
            ulonglong2 a01 = ar[0];
            ulonglong2 a23 = ar[1];
            ulonglong2 w = *(const ulonglong2*)&Wsf[buf][kk][tx * 4];
            acc[0][0] = fma2(a01.x, w.x, acc[0][0]); acc[0][1] = fma2(a01.x, w.y, acc[0][1]);
            acc[1][0] = fma2(a01.y, w.x, acc[1][0]); acc[1][1] = fma2(a01.y, w.y, acc[1][1]);
            acc[2][0] = fma2(a23.x, w.x, acc[2][0]); acc[2][1] = fma2(a23.x, w.y, acc[2][1]);
            acc[3][0] = fma2(a23.y, w.x, acc[3][0]); acc[3][1] = fma2(a23.y, w.y, acc[3][1]);
        }
        if (more) store(buf ^ 1, a4, w4);
        __syncthreads();
        buf ^= 1;
        g = gn;
    }

    float* dst = part + (size_t)sp * 64 * ldo;
#pragma unroll
    for (int i = 0; i < 4; i++) {
        int m = ty * 4 + i;
        float2 r0 = unpack2(acc[i][0]);
        float2 r1 = unpack2(acc[i][1]);
        float4 v = make_float4(r0.x, r0.y, r1.x, r1.y);
        *(float4*)(dst + (size_t)m * ldo + j0 + tx * 4) = v;
    }
}

// ---------------- LSTM pointwise fused with split reduce ----------------
__global__ void lstm_point_k(const float* part, int nsplit,
                             const float* b1, const float* b2,
                             const float* c_in, float* h_out, float* c_out) {
    int idx = blockIdx.x * 256 + threadIdx.x;  // 64*1024
    int b = idx >> 10, r = idx & 1023;
    size_t base = (size_t)b * 4096;
    float g[4];
#pragma unroll
    for (int gt = 0; gt < 4; gt++) g[gt] = b1[gt * 1024 + r] + b2[gt * 1024 + r];
    for (int p = 0; p < nsplit; p++) {
        const float* pp = part + (size_t)p * BB * 4096 + base + r;
#pragma unroll
        for (int gt = 0; gt < 4; gt++) g[gt] += pp[gt * 1024];
    }
    float c  = c_in[idx];
    float c2 = sigmoidf(g[1]) * c + sigmoidf(g[0]) * tanhf(g[2]);
    float h2 = sigmoidf(g[3]) * tanhf(c2);
    c_out[idx] = c2;
    h_out[idx] = h2;
}

// ---------------- pq: one warp per output, K=1024 ----------------
__global__ __launch_bounds__(256) void pq_k(const float* ah, const float* Wq, float* pq) {
    int gid  = blockIdx.x * 8 + (threadIdx.x >> 5);
    int lane = threadIdx.x & 31;
    int m = gid >> 7, n = gid & 127;
    const float4* a = (const float4*)(ah + (size_t)m * RR);
    const float4* w = (const float4*)(Wq + (size_t)n * RR);
    float s = 0.f;
#pragma unroll
    for (int i = 0; i < 8; i++) {
        float4 x = a[lane + 32 * i];
        float4 y = w[lane + 32 * i];
        s += x.x * y.x + x.y * y.y + x.z * y.z + x.w * y.w;
    }
#pragma unroll
    for (int off = 16; off > 0; off >>= 1) s += __shfl_xor_sync(0xFFFFFFFFu, s, off);
    if (lane == 0) pq[m * AA + n] = s;
}

// ---------------- fused conv(31)+FC+tanh energy + block softmax stats ----------------
__global__ __launch_bounds__(256) void energies_k(
        const float* att_w, const float* att_w_cum,
        const float* pm, const float* pq,
        const float* W_loc, const float* W_lfc,
        const float* W_v, const void* mask, float* energy) {
    __shared__ float s_aw0[256 + 30];
    __shared__ float s_aw1[256 + 30];
    __shared__ float s_pq[AA];
    __shared__ float s_wv[AA];
    __shared__ ulonglong2 s_wl2[2][KK][8];
    __shared__ ulonglong2 s_wlfc2[AA][8];
    __shared__ float red[256];

    int tid = threadIdx.x;
    int b = blockIdx.y;
    int t0 = blockIdx.x * 256;
    int t = t0 + tid;

    for (int i = tid; i < 286; i += 256) {
        int gidx = t0 - PAD + i;
        bool inb = (gidx >= 0 && gidx < TT);
        s_aw0[i] = inb ? att_w[(size_t)b * TT + gidx] : 0.f;
        s_aw1[i] = inb ? att_w_cum[(size_t)b * TT + gidx] : 0.f;
    }
    for (int i = tid; i < 2 * KK * 16; i += 256) {
        int c = i / (KK * 16);
        int r = i % (KK * 16);
        int k = r / 16, fp = r % 16;
        float lo = W_loc[(2 * fp + 0) * (2 * KK) + c * KK + k];
        float hi = W_loc[(2 * fp + 1) * (2 * KK) + c * KK + k];
        ((ull*)s_wl2)[c * KK * 16 + k * 16 + fp] = pack2(lo, hi);
    }
    for (int i = tid; i < AA * 8; i += 256)
        ((ulonglong2*)s_wlfc2)[i] = ((const ulonglong2*)W_lfc)[i];
    if (tid < AA) { s_pq[tid] = pq[b * AA + tid]; s_wv[tid] = W_v[tid]; }
    __syncthreads();

    ull locf2[16];
#pragma unroll
    for (int i = 0; i < 16; i++) locf2[i] = 0ull;
    for (int k = 0; k < KK; k++) {
        ull a0 = pack2(s_aw0[tid + k], s_aw0[tid + k]);
        ull a1 = pack2(s_aw1[tid + k], s_aw1[tid + k]);
#pragma unroll
        for (int i = 0; i < 8; i++) {
            ulonglong2 w0 = s_wl2[0][k][i];
            ulonglong2 w1 = s_wl2[1][k][i];
            locf2[2 * i]     = fma2(a0, w0.x, locf2[2 * i]);
            locf2[2 * i + 1] = fma2(a0, w0.y, locf2[2 * i + 1]);
            locf2[2 * i]     = fma2(a1, w1.x, locf2[2 * i]);
            locf2[2 * i + 1] = fma2(a1, w1.y, locf2[2 * i + 1]);
        }
    }

    const float2* pmrow2 = (const float2*)(pm + ((size_t)b * TT + t) * AA);
    float e = 0.f;
    for (int a = 0; a < AA; a += 2) {
        ull ac0 = 0ull, ac1 = 0ull, ac2 = 0ull, ac3 = 0ull;
#pragma unroll
        for (int i = 0; i < 8; i++) {
            ulonglong2 w0 = s_wlfc2[a][i];
            ulonglong2 w1 = s_wlfc2[a + 1][i];
            ac0 = fma2(locf2[2 * i],     w0.x, ac0);
            ac1 = fma2(locf2[2 * i + 1], w0.y, ac1);
            ac2 = fma2(locf2[2 * i],     w1.x, ac2);
            ac3 = fma2(locf2[2 * i + 1], w1.y, ac3);
        }
        float2 f0 = unpack2(ac0), f1 = unpack2(ac1);
        float2 f2 = unpack2(ac2), f3 = unpack2(ac3);
        float la0 = (f0.x + f0.y) + (f1.x + f1.y);
        float la1 = (f2.x + f2.y) + (f3.x + f3.y);
        float2 p = pmrow2[a >> 1];
        float x0 = s_pq[a] + p.x + la0;
        float x1 = s_pq[a + 1] + p.y + la1;
        e += tanhfast(x0) * s_wv[a];
        e += tanhfast(x1) * s_wv[a + 1];
    }

    size_t mi = (size_t)b * TT + t;
    int mm = g_maskmode;
    bool masked;
    if (mm == 0)      masked = (((const int*)mask)[mi] != 0);
    else if (mm == 1) masked = (((const float*)mask)[mi] != 0.f);
    else              masked = (((const unsigned char*)mask)[mi] != 0);
    e = masked ? NEG_INF : e;
    energy[mi] = e;

    // block softmax stats: local max and sum of exp(e - max)
    red[tid] = e; __syncthreads();
    for (int s = 128; s > 0; s >>= 1) {
        if (tid < s) red[tid] = fmaxf(red[tid], red[tid + s]);
        __syncthreads();
    }
    float Mc = red[0]; __syncthreads();
    red[tid] = __expf(e - Mc); __syncthreads();
    for (int s = 128; s > 0; s >>= 1) {
        if (tid < s) red[tid] += red[tid + s];
        __syncthreads();
    }
    if (tid == 0) {
        g_bm[b * 8 + blockIdx.x] = Mc;
        g_bs[b * 8 + blockIdx.x] = red[0];
    }
}

// ---------------- combine softmax stats ----------------
__global__ void combine_k() {
    int b = threadIdx.x;  // 64 threads
    float M = -3.0e38f;
#pragma unroll
    for (int c = 0; c < 8; c++) M = fmaxf(M, g_bm[b * 8 + c]);
    float S = 0.f;
#pragma unroll
    for (int c = 0; c < 8; c++) S += g_bs[b * 8 + c] * __expf(g_bm[b * 8 + c] - M);
    g_M[b] = M;
    g_inv[b] = 1.0f / S;
}

// ---------------- context partials (normalizes + writes w_out) ----------------
__global__ void ctx_part_k(const float* energy, float* w_out, const float* memory) {
    __shared__ float s_w[256];
    int b = blockIdx.y, tc = blockIdx.x, e = threadIdx.x;
    int t0 = tc * 256;
    float M = g_M[b], inv = g_inv[b];
    float w = __expf(energy[(size_t)b * TT + t0 + e] - M) * inv;
    s_w[e] = w;
    w_out[(size_t)b * TT + t0 + e] = w;
    __syncthreads();
    const float* mrow = memory + ((size_t)b * TT + t0) * EE + e;
    float a0 = 0.f, a1 = 0.f, a2 = 0.f, a3 = 0.f;
    for (int i = 0; i < 256; i += 4) {
        a0 += s_w[i + 0] * mrow[(size_t)(i + 0) * EE];
        a1 += s_w[i + 1] * mrow[(size_t)(i + 1) * EE];
        a2 += s_w[i + 2] * mrow[(size_t)(i + 2) * EE];
        a3 += s_w[i + 3] * mrow[(size_t)(i + 3) * EE];
    }
    g_ctx_part[((size_t)b * 8 + tc) * EE + e] = (a0 + a1) + (a2 + a3);
}

__global__ void ctx_red_k() {
    int b = blockIdx.x, e = threadIdx.x;
    float s = 0.f;
#pragma unroll
    for (int p = 0; p < 8; p++) s += g_ctx_part[((size_t)b * 8 + p) * EE + e];
    g_ctx[b * EE + e] = s;
}

// ---------------- proj + stop: one warp per output, K=1280 ----------------
__global__ __launch_bounds__(256) void projstop_k(
        const float* W_proj, const float* b_proj,
        const float* W_gate, const float* b_gate,
        float* out, float* stop_out) {
    int gid  = blockIdx.x * 8 + (threadIdx.x >> 5);
    int lane = threadIdx.x & 31;
    bool is_stop = (gid >= BB * HH);
    int m, h;
    const float4* w;
    if (!is_stop) {
        m = gid >> 8; h = gid & 255;
        w = (const float4*)(W_proj + (size_t)h * (DD + EE));
    } else {
        m = gid - BB * HH;
        if (m >= BB) return;
        h = 0;
        w = (const float4*)W_gate;
    }
    const float4* a1 = (const float4*)(g_dh + (size_t)m * DD);
    const float4* a2 = (const float4*)(g_ctx + (size_t)m * EE);
    float s = 0.f;
#pragma unroll
    for (int i = 0; i < 8; i++) {
        float4 x = a1[lane + 32 * i];
        float4 y = w[lane + 32 * i];
        s += x.x * y.x + x.y * y.y + x.z * y.z + x.w * y.w;
    }
#pragma unroll
    for (int i = 0; i < 2; i++) {
        float4 x = a2[lane + 32 * i];
        float4 y = w[256 + lane + 32 * i];
        s += x.x * y.x + x.y * y.y + x.z * y.z + x.w * y.w;
    }
#pragma unroll
    for (int off = 16; off > 0; off >>= 1) s += __shfl_xor_sync(0xFFFFFFFFu, s, off);
    if (lane == 0) {
        if (!is_stop) out[gid] = s + b_proj[h];
        else          stop_out[m] = s + b_gate[0];
    }
}

// ---------------- launch ----------------
extern "C" void kernel_launch(void* const* d_in, const int* in_sizes, int n_in,
                              void* d_out, int out_size) {
    const float* last_frame = (const float*)d_in[0];
    const float* att_h      = (const float*)d_in[1];
    const float* att_c      = (const float*)d_in[2];
    const float* att_w      = (const float*)d_in[3];
    const float* att_w_cum  = (const float*)d_in[4];
    const float* att_ctx    = (const float*)d_in[5];
    const float* dec_h      = (const float*)d_in[6];
    const float* dec_c      = (const float*)d_in[7];
    const float* memory     = (const float*)d_in[8];
    const float* pm         = (const float*)d_in[9];
    const float* W_ih_a     = (const float*)d_in[10];
    const float* W_hh_a     = (const float*)d_in[11];
    const float* b_ih_a     = (const float*)d_in[12];
    const float* b_hh_a     = (const float*)d_in[13];
    const float* W_q        = (const float*)d_in[14];
    const float* W_v        = (const float*)d_in[15];
    const float* W_loc      = (const float*)d_in[16];
    const float* W_lfc      = (const float*)d_in[17];
    const float* W_ih_d     = (const float*)d_in[18];
    const float* W_hh_d     = (const float*)d_in[19];
    const float* b_ih_d     = (const float*)d_in[20];
    const float* b_hh_d     = (const float*)d_in[21];
    const float* W_proj     = (const float*)d_in[22];
    const float* b_proj     = (const float*)d_in[23];
    const float* W_gate     = (const float*)d_in[24];
    const float* b_gate     = (const float*)d_in[25];
    const void*  mask       = d_in[26];

    float* out      = (float*)d_out;                // decoder_output [64,256]
    float* stop_out = out + BB * HH;                // [64]
    float* w_out    = out + BB * HH + BB;           // weights [64,2048]

    float *p_part, *p_ah, *p_ac, *p_dh, *p_dc, *p_pq, *p_energy, *p_ctx;
    cudaGetSymbolAddress((void**)&p_part, g_part);
    cudaGetSymbolAddress((void**)&p_ah, g_ah);
    cudaGetSymbolAddress((void**)&p_ac, g_ac);
    cudaGetSymbolAddress((void**)&p_dh, g_dh);
    cudaGetSymbolAddress((void**)&p_dc, g_dc);
    cudaGetSymbolAddress((void**)&p_pq, g_pq);
    cudaGetSymbolAddress((void**)&p_energy, g_energy);
    cudaGetSymbolAddress((void**)&p_ctx, g_ctx);

    detect_mask_k<<<1, 256>>>((const unsigned int*)mask);

    // attention LSTM gates (splitK=8 -> 512 blocks)
    {
        Segs3 s{}; s.n = 3;
        s.s[0] = { last_frame, W_ih_a,      PP, PP + EE, PP };
        s.s[1] = { att_ctx,    W_ih_a + PP, EE, PP + EE, EE };
        s.s[2] = { att_h,      W_hh_a,      RR, RR,      RR };
        gemm64s<<<dim3(4 * RR / 64, 8), 256>>>(s, p_part, 4 * RR, 8);
    }
    lstm_point_k<<<BB * RR / 256, 256>>>(p_part, 8, b_ih_a, b_hh_a, att_c, p_ah, p_ac);

    pq_k<<<BB * AA / 8, 256>>>(p_ah, W_q, p_pq);

    energies_k<<<dim3(TT / 256, BB), 256>>>(att_w, att_w_cum, pm, p_pq,
                                            W_loc, W_lfc, W_v, mask, p_energy);
    combine_k<<<1, 64>>>();
    ctx_part_k<<<dim3(8, BB), 256>>>(p_energy, w_out, memory);
    ctx_red_k<<<BB, EE>>>();

    // decoder LSTM gates (splitK=8 -> 512 blocks)
    {
        Segs3 s{}; s.n = 3;
        s.s[0] = { p_ah,  W_ih_d,      RR, RR + EE, RR };
        s.s[1] = { p_ctx, W_ih_d + RR, EE, RR + EE, EE };
        s.s[2] = { dec_h, W_hh_d,      DD, DD,      DD };
        gemm64s<<<dim3(4 * DD / 64, 8), 256>>>(s, p_part, 4 * DD, 8);
    }
    lstm_point_k<<<BB * DD / 256, 256>>>(p_part, 8, b_ih_d, b_hh_d, dec_c, p_dh, p_dc);

    projstop_k<<<(BB * HH + BB + 7) / 8, 256>>>(W_proj, b_proj, W_gate, b_gate,
                                                out, stop_out);
}